// round 7
// baseline (speedup 1.0000x reference)
#include <cuda_runtime.h>
#include <cstdint>
#include <cstddef>

// Problem constants
#define NEMB   1024
#define EDIM   256
#define BATCH  8
#define HWL    4096
#define NROWS  32768
#define MT     128
#define NBLK   256
#define APITCH 260           // 260 % 32 == 4 -> conflict-free fragment loads
#define BPITCH 68            // 68 % 32 == 4
#define NCHW   128           // codes per n-chunk
#define KCH    64            // dims per k-chunk
#define TOTCH  32            // 8 n-chunks * 4 k-chunks
#define CAP    4096
#define EPS    4e-3f

// smem byte offsets
#define SM_A     0
#define SM_B     133120
#define BBYTES   34816
#define SM_Z2    202752
#define SM_E2    203264
#define SM_V     203776
#define SM_BEST  204800
#define SM_CAND  205824
#define SM_CNT   222208
#define SM_TOTAL 222224

// Scratch
__device__ float  g_zf[NROWS*EDIM];
__device__ float  g_e2[NEMB];
__device__ int    g_idx[NROWS];
__device__ double g_partial[NBLK];

// ---------------- helpers ----------------
__device__ __forceinline__ uint32_t smem_u32(const void* p) {
    uint32_t a;
    asm("{ .reg .u64 t; cvta.to.shared.u64 t, %1; cvt.u32.u64 %0, t; }" : "=r"(a) : "l"(p));
    return a;
}
__device__ __forceinline__ unsigned f2tf(float x) {
    unsigned r; asm("cvt.rna.tf32.f32 %0, %1;" : "=r"(r) : "f"(x)); return r;
}
__device__ __forceinline__ void mma_tf32(float* c, const uint32_t* a, const uint32_t* b) {
    asm volatile("mma.sync.aligned.m16n8k8.row.col.f32.tf32.tf32.f32 "
        "{%0,%1,%2,%3}, {%4,%5,%6,%7}, {%8,%9}, {%0,%1,%2,%3};"
        : "+f"(c[0]), "+f"(c[1]), "+f"(c[2]), "+f"(c[3])
        : "r"(a[0]), "r"(a[1]), "r"(a[2]), "r"(a[3]), "r"(b[0]), "r"(b[1]));
}
__device__ __forceinline__ void cpa16(uint32_t dst, const void* src) {
    asm volatile("cp.async.cg.shared.global [%0], [%1], 16;" :: "r"(dst), "l"(src));
}
#define CP_COMMIT() asm volatile("cp.async.commit_group;" ::: "memory")
#define CP_WAIT1()  asm volatile("cp.async.wait_group 1;" ::: "memory")
#define CP_WAIT0()  asm volatile("cp.async.wait_group 0;" ::: "memory")

// exact fp32 distance (identical pipeline to the R2/R3 passing kernels)
__device__ __forceinline__ float exact_dist(int nrow, int k, float z2r,
                                            const float* __restrict__ cb) {
    const float* zr = g_zf + (size_t)nrow*EDIM;
    const float* er = cb   + (size_t)k*EDIM;
    float s0 = 0.f, s1 = 0.f;
    #pragma unroll 8
    for (int d = 0; d < EDIM; d += 2) {
        s0 += zr[d]   * er[d];
        s1 += zr[d+1] * er[d+1];
    }
    return (z2r + g_e2[k]) - 2.f*(s0 + s1);
}

// ---------------------------------------------------------------------------
// Kernel A: transpose z (B, D, HWL) -> zf (B*HWL, D)
// ---------------------------------------------------------------------------
__global__ void vq_transpose(const float* __restrict__ z) {
    __shared__ float tile[32][33];
    int b = blockIdx.z, d0 = blockIdx.y << 5, s0 = blockIdx.x << 5;
    int tx = threadIdx.x, ty = threadIdx.y;
    const float* src = z + ((size_t)b*EDIM + d0)*HWL + s0;
    #pragma unroll
    for (int i = 0; i < 32; i += 8)
        tile[ty+i][tx] = src[(size_t)(ty+i)*HWL + tx];
    __syncthreads();
    float* dst = g_zf + ((size_t)b*HWL + s0)*EDIM + d0;
    #pragma unroll
    for (int i = 0; i < 32; i += 8)
        dst[(size_t)(ty+i)*EDIM + tx] = tile[tx][ty+i];
}

// ---------------------------------------------------------------------------
// Kernel B: codebook row norms (double accumulate -> correctly rounded fp32)
// ---------------------------------------------------------------------------
__global__ void vq_e2(const float* __restrict__ cb) {
    int k = blockIdx.x * blockDim.x + threadIdx.x;
    if (k < NEMB) {
        const float* row = cb + (size_t)k*EDIM;
        double s = 0.0;
        for (int d = 0; d < EDIM; d++) { double v = row[d]; s += v*v; }
        g_e2[k] = (float)s;
    }
}

// ---------------------------------------------------------------------------
// B-chunk loader: 128 codes x 64 dims via cp.async (double buffered)
// ---------------------------------------------------------------------------
__device__ __forceinline__ void load_chunk(uint32_t sb, const float* __restrict__ cb,
                                           int cc, int t) {
    int nc = cc >> 2, kc = cc & 3, buf = cc & 1;
    const float* src = cb + (size_t)(nc*NCHW)*EDIM + kc*KCH;
    uint32_t dst = sb + SM_B + buf*BBYTES;
    #pragma unroll
    for (int j = 0; j < 8; j++) {
        int i = t + j*256;
        int n = i >> 4, q = i & 15;
        cpa16(dst + (uint32_t)(n*BPITCH + q*4)*4, src + (size_t)n*EDIM + q*4);
    }
    CP_COMMIT();
}

// ---------------------------------------------------------------------------
// Kernel C: tf32 mma.sync GEMM + running-min screening + exact rescore
// ---------------------------------------------------------------------------
__global__ __launch_bounds__(256, 1)
void vq_main(const float* __restrict__ cb, float* __restrict__ out_idx, int write_idx) {
    extern __shared__ char smc[];
    uint32_t sb = smem_u32(smc);
    uint32_t* As  = (uint32_t*)(smc + SM_A);
    float* z2s = (float*)(smc + SM_Z2);
    float* e2s = (float*)(smc + SM_E2);
    float* V   = (float*)(smc + SM_V);       // [2][128] per col-warp running row min
    unsigned long long* best = (unsigned long long*)(smc + SM_BEST);
    unsigned* cand = (unsigned*)(smc + SM_CAND);
    int* scnt = (int*)(smc + SM_CNT);

    const int t = threadIdx.x, lane = t & 31, w = t >> 5;
    const int rw = w >> 1, cw = w & 1;
    const int g = lane >> 2, qq = lane & 3;
    const int n0 = blockIdx.x * MT;

    // init
    if (t < MT) { V[t] = 3.4e38f; V[MT + t] = 3.4e38f; best[t] = ~0ull; }
    if (t == 0) *scnt = 0;

    // prologue B prefetch
    load_chunk(sb, cb, 0, t);
    load_chunk(sb, cb, 1, t);

    // A tile -> smem, tf32 converted (resident all kernel)
    for (int i = t; i < MT*(EDIM/4); i += 256) {
        int r = i >> 6, c4 = (i & 63) << 2;
        float4 v = *(const float4*)(g_zf + (size_t)(n0 + r)*EDIM + c4);
        uint32_t* d = As + r*APITCH + c4;
        d[0] = f2tf(v.x); d[1] = f2tf(v.y); d[2] = f2tf(v.z); d[3] = f2tf(v.w);
    }

    // exact z2 per row (same arithmetic as passing R2/R3 kernel)
    {
        int r = t >> 1, h = t & 1;
        const float* row = g_zf + (size_t)(n0 + r)*EDIM + h*128;
        float s = 0.f;
        #pragma unroll 8
        for (int d = 0; d < 128; d++) s += row[d]*row[d];
        float o = __shfl_xor_sync(0xffffffffu, s, 1);
        if (!h) z2s[r] = s + o;
    }

    float acc[2][8][4];

    for (int cc = 0; cc < TOTCH; cc++) {
        int nc = cc >> 2, kc = cc & 3, buf = cc & 1;
        if (cc + 1 < TOTCH) CP_WAIT1(); else CP_WAIT0();
        __syncthreads();                 // B(cc) visible; also covers init/A on cc==0

        if (kc == 0) {
            if (t < NCHW) e2s[t] = g_e2[nc*NCHW + t];   // read at kc==3, syncs cover
            #pragma unroll
            for (int rt = 0; rt < 2; rt++)
                #pragma unroll
                for (int ct = 0; ct < 8; ct++)
                    #pragma unroll
                    for (int u = 0; u < 4; u++) acc[rt][ct][u] = 0.f;
        }

        const uint32_t* Bs = (const uint32_t*)(smc + SM_B + buf*BBYTES);
        const uint32_t* Ab = As + (rw*32 + g)*APITCH + kc*KCH + qq;
        const uint32_t* Bb = Bs + (cw*64 + g)*BPITCH + qq;

        #pragma unroll
        for (int ks = 0; ks < 8; ks++) {
            const int kb = ks*8;
            uint32_t a[2][4], b[8][2];
            #pragma unroll
            for (int ct = 0; ct < 8; ct++) {
                b[ct][0] = Bb[ct*8*BPITCH + kb];
                b[ct][1] = Bb[ct*8*BPITCH + kb + 4];
            }
            #pragma unroll
            for (int rt = 0; rt < 2; rt++) {
                const uint32_t* ap = Ab + rt*16*APITCH + kb;
                a[rt][0] = ap[0];
                a[rt][1] = ap[8*APITCH];
                a[rt][2] = ap[4];
                a[rt][3] = ap[8*APITCH + 4];
            }
            #pragma unroll
            for (int rt = 0; rt < 2; rt++)
                #pragma unroll
                for (int ct = 0; ct < 8; ct++)
                    mma_tf32(acc[rt][ct], a[rt], b[ct]);
        }

        if (kc == 3) {
            // 1) per-row chunk min -> update running min V (single writer per slot)
            #pragma unroll
            for (int rt = 0; rt < 2; rt++)
                #pragma unroll
                for (int h = 0; h < 2; h++) {
                    int row = rw*32 + rt*16 + g + h*8;
                    float z2r = z2s[row];
                    float m = 3.4e38f;
                    #pragma unroll
                    for (int ct = 0; ct < 8; ct++) {
                        int colc = cw*64 + ct*8 + 2*qq;
                        float d0 = (z2r + e2s[colc])   - 2.f*acc[rt][ct][2*h];
                        float d1 = (z2r + e2s[colc+1]) - 2.f*acc[rt][ct][2*h+1];
                        m = fminf(m, fminf(d0, d1));
                    }
                    m = fminf(m, __shfl_xor_sync(0xffffffffu, m, 1));
                    m = fminf(m, __shfl_xor_sync(0xffffffffu, m, 2));
                    if (qq == 0) {
                        float* vp = V + cw*MT + row;
                        *vp = fminf(*vp, m);
                    }
                }
            __syncwarp();
            // 2) candidate scan vs running min (+eps): superset of true argmin
            #pragma unroll
            for (int rt = 0; rt < 2; rt++)
                #pragma unroll
                for (int h = 0; h < 2; h++) {
                    int row = rw*32 + rt*16 + g + h*8;
                    float z2r = z2s[row];
                    float thr = fminf(V[row], V[MT + row]) + EPS;
                    #pragma unroll
                    for (int ct = 0; ct < 8; ct++)
                        #pragma unroll
                        for (int c01 = 0; c01 < 2; c01++) {
                            int colc = cw*64 + ct*8 + 2*qq + c01;
                            float dd = (z2r + e2s[colc]) - 2.f*acc[rt][ct][2*h + c01];
                            if (dd <= thr) {
                                int k = nc*NCHW + colc;
                                int idx = atomicAdd(scnt, 1);
                                if (idx < CAP) {
                                    cand[idx] = ((unsigned)row << 16) | (unsigned)k;
                                } else {
                                    // overflow fallback: rescore inline (correct, slow, rare)
                                    float de = exact_dist(n0 + row, k, z2r, cb);
                                    unsigned long long key =
                                        ((unsigned long long)__float_as_uint(de) << 32) | (unsigned)k;
                                    atomicMin(best + row, key);
                                }
                            }
                        }
                }
        }
        __syncthreads();                 // all reads of buf done before re-fill
        if (cc + 2 < TOTCH) load_chunk(sb, cb, cc + 2, t);
    }

    __syncthreads();
    // cooperative exact rescore of candidates
    int cnt = *scnt; if (cnt > CAP) cnt = CAP;
    for (int i = t; i < cnt; i += 256) {
        unsigned pk = cand[i];
        int row = (int)(pk >> 16), k = (int)(pk & 0xFFFFu);
        float de = exact_dist(n0 + row, k, z2s[row], cb);
        unsigned long long key = ((unsigned long long)__float_as_uint(de) << 32) | (unsigned)k;
        atomicMin(best + row, key);      // positive fp32: bit-monotonic; ties -> smaller k
    }
    __syncthreads();

    float* vmin = e2s;                   // reuse
    if (t < MT) {
        unsigned long long kb = best[t];
        int k = (int)(kb & 0xFFFFFFFFull);
        g_idx[n0 + t] = k;
        if (write_idx) out_idx[n0 + t] = (float)k;
        vmin[t] = __uint_as_float((unsigned)(kb >> 32));
    }
    __syncthreads();
    if (t == 0) {
        double s = 0.0;
        for (int r = 0; r < MT; r++) s += (double)vmin[r];
        g_partial[blockIdx.x] = s;       // deterministic
    }
}

// ---------------------------------------------------------------------------
// Kernel D: gather codebook rows by index, write (B, D, HWL)
// ---------------------------------------------------------------------------
__global__ __launch_bounds__(256)
void vq_scatter(const float* __restrict__ cb, float* __restrict__ outq) {
    __shared__ float qt[32*257];
    int b = blockIdx.y, s0 = blockIdx.x << 5, t = threadIdx.x;
    for (int i = t; i < 32*64; i += 256) {
        int r = i >> 6, c4 = i & 63;
        int k = g_idx[b*HWL + s0 + r];
        float4 v = *(const float4*)(cb + (size_t)k*EDIM + (c4 << 2));
        float* dst = qt + r*257 + (c4 << 2);
        dst[0] = v.x; dst[1] = v.y; dst[2] = v.z; dst[3] = v.w;
    }
    __syncthreads();
    int s = t & 31, dh = t >> 5;
    #pragma unroll
    for (int d = dh; d < EDIM; d += 8)
        outq[((size_t)b*EDIM + d)*HWL + s0 + s] = qt[s*257 + d];
}

// ---------------------------------------------------------------------------
// Kernel E: loss = 1.25 * sum(min_dist) / (N*D)
// ---------------------------------------------------------------------------
__global__ void vq_finalize(float* out_loss) {
    double s = 0.0;
    for (int i = 0; i < NBLK; i++) s += g_partial[i];
    *out_loss = (float)(1.25 * s / (double)((size_t)NROWS*EDIM));
}

// ---------------------------------------------------------------------------
extern "C" void kernel_launch(void* const* d_in, const int* in_sizes, int n_in,
                              void* d_out, int out_size) {
    const float* z  = (const float*)d_in[0];
    const float* cb = (const float*)d_in[1];
    if (n_in >= 2 && in_sizes[0] == NEMB*EDIM && in_sizes[1] == NROWS*EDIM) {
        const float* tmp = z; z = cb; cb = tmp;
    }
    float* out = (float*)d_out;

    const int QN = NROWS*EDIM;
    bool has_quant = (out_size >= QN);
    bool full      = (out_size == QN + NROWS + 1);
    float* out_idx  = full ? out + QN         : nullptr;
    float* out_loss = full ? out + QN + NROWS : nullptr;

    cudaFuncSetAttribute(vq_main, cudaFuncAttributeMaxDynamicSharedMemorySize, SM_TOTAL);

    vq_transpose<<<dim3(HWL/32, EDIM/32, BATCH), dim3(32, 8)>>>(z);
    vq_e2<<<(NEMB + 255)/256, 256>>>(cb);
    vq_main<<<NBLK, 256, SM_TOTAL>>>(cb, out_idx, full ? 1 : 0);
    if (has_quant)
        vq_scatter<<<dim3(HWL/32, BATCH), 256>>>(cb, out);
    if (full)
        vq_finalize<<<1, 1>>>(out_loss);
}